// round 1
// baseline (speedup 1.0000x reference)
#include <cuda_runtime.h>
#include <math.h>

#define Bb 8
#define Ss 2048
#define Dh 256
#define Hh 8
#define BQ 64
#define BK 64

// Folded output projection: Wt[j][d] = sum_h W_o[d][h*256 + j]
__device__ float g_Wt[Dh * Dh];

__global__ void wt_kernel(const float* __restrict__ W_o) {
    int d = blockIdx.x;   // 0..255
    int j = threadIdx.x;  // 0..255
    float s = 0.f;
#pragma unroll
    for (int h = 0; h < Hh; h++) s += W_o[d * (Dh * Hh) + h * Dh + j];
    g_Wt[j * Dh + d] = s;
}

// Shared memory layout (floats)
#define OFF_Q  0
#define OFF_KT (BQ * Dh)                      // 16384
#define OFF_E  (OFF_KT + Dh * 65)             // 16384 + 16640
#define OFF_P  (OFF_E + BK * Dh)              // + 16384
#define SMEM_FLOATS (OFF_P + BQ * 65)         // + 4160 = 53568 floats = 214272 B

extern __shared__ float sm[];

__global__ __launch_bounds__(256, 1) void attn_kernel(
    const float* __restrict__ e,
    const float* __restrict__ p,
    float* __restrict__ out)
{
    const int qb = blockIdx.x;
    const int b  = blockIdx.y;
    const int q0 = qb * BQ;
    const int tid = threadIdx.x;
    const int tx = tid & 15;
    const int ty = tid >> 4;

    float* q_s  = sm + OFF_Q;   // [64][256] row-major (reused as y_s in epilogue)
    float* kT_s = sm + OFF_KT;  // [256][65] transposed K
    float* e_s  = sm + OFF_E;   // [64][256] (reused as W chunk in epilogue)
    float* P_s  = sm + OFF_P;   // [64][65]

    // ---- Load Q tile: q row r = p[b][1 + q0 + r][:] ----
    {
        const float4* src = (const float4*)(p + ((b * (Ss + 1) + 1 + q0)) * Dh);
        float4* dst = (float4*)q_s;
        for (int i = tid; i < BQ * Dh / 4; i += 256) dst[i] = src[i];
    }

    float yacc[4][16];
    float den[4];
#pragma unroll
    for (int a = 0; a < 4; a++) {
        den[a] = 0.f;
#pragma unroll
        for (int c = 0; c < 16; c++) yacc[a][c] = 0.f;
    }

    const float scale = 0.0625f;  // 1/sqrt(256)

    for (int kb = 0; kb <= qb; kb++) {
        const int k0 = kb * BK;
        __syncthreads();  // protect q_s (iter 0) and kT/e/P reuse

        // Load E tile (row-major, coalesced)
        {
            const float4* src = (const float4*)(e + (b * Ss + k0) * Dh);
            float4* dst = (float4*)e_s;
            for (int i = tid; i < BK * Dh / 4; i += 256) dst[i] = src[i];
        }
        // Load K tile transposed: key j is p[b][j][:]
        {
            const float4* src = (const float4*)(p + (b * (Ss + 1) + k0) * Dh);
            for (int i = tid; i < BK * Dh / 4; i += 256) {
                int c  = i >> 6;   // key row within tile (64 float4 per row)
                int d4 = i & 63;
                float4 v = src[c * 64 + d4];
                int d = d4 * 4;
                kT_s[(d + 0) * 65 + c] = v.x;
                kT_s[(d + 1) * 65 + c] = v.y;
                kT_s[(d + 2) * 65 + c] = v.z;
                kT_s[(d + 3) * 65 + c] = v.w;
            }
        }
        __syncthreads();

        // ---- Scores: S[64x64] = Q . K^T ----
        float sacc[4][4];
#pragma unroll
        for (int a = 0; a < 4; a++)
#pragma unroll
            for (int c = 0; c < 4; c++) sacc[a][c] = 0.f;

#pragma unroll 4
        for (int d = 0; d < Dh; d++) {
            float qv[4], kv[4];
#pragma unroll
            for (int a = 0; a < 4; a++) qv[a] = q_s[(16 * a + ty) * Dh + d];
#pragma unroll
            for (int c = 0; c < 4; c++) kv[c] = kT_s[d * 65 + 16 * c + tx];
#pragma unroll
            for (int a = 0; a < 4; a++)
#pragma unroll
                for (int c = 0; c < 4; c++) sacc[a][c] = fmaf(qv[a], kv[c], sacc[a][c]);
        }

        // clip, causal mask, exp -> P_s
#pragma unroll
        for (int a = 0; a < 4; a++) {
            int qpos = q0 + 16 * a + ty;
#pragma unroll
            for (int c = 0; c < 4; c++) {
                int kpos = k0 + 16 * c + tx;
                float s = sacc[a][c] * scale;
                s = fminf(fmaxf(s, -10.f), 10.f);
                float pv = (kpos <= qpos) ? __expf(s) : 0.f;
                P_s[(16 * a + ty) * 65 + 16 * c + tx] = pv;
            }
        }
        __syncthreads();

        // ---- AV: y += P . E, den += rowsum(P) ----
#pragma unroll 2
        for (int kk = 0; kk < BK; kk++) {
            float pv[4], ev[16];
#pragma unroll
            for (int a = 0; a < 4; a++) pv[a] = P_s[(16 * a + ty) * 65 + kk];
#pragma unroll
            for (int c = 0; c < 16; c++) ev[c] = e_s[kk * Dh + tx + 16 * c];
#pragma unroll
            for (int a = 0; a < 4; a++) {
                den[a] += pv[a];
#pragma unroll
                for (int c = 0; c < 16; c++) yacc[a][c] = fmaf(pv[a], ev[c], yacc[a][c]);
            }
        }
    }

    // ---- Normalize: 1/(den * (qpos+1)) ----
#pragma unroll
    for (int a = 0; a < 4; a++) {
        float inv = 1.f / (den[a] * (float)(q0 + 16 * a + ty + 1));
#pragma unroll
        for (int c = 0; c < 16; c++) yacc[a][c] *= inv;
    }

    // ---- Epilogue: out = y @ Wt (Wt[j][d], j summed) ----
    // write y into q_s region, zero accumulators
#pragma unroll
    for (int a = 0; a < 4; a++)
#pragma unroll
        for (int c = 0; c < 16; c++) {
            q_s[(16 * a + ty) * Dh + tx + 16 * c] = yacc[a][c];
            yacc[a][c] = 0.f;
        }
    __syncthreads();

    for (int jb = 0; jb < 4; jb++) {
        const int j0 = jb * 64;
        // load Wt rows j0..j0+63 into e_s region
        {
            const float4* src = (const float4*)(g_Wt + j0 * Dh);
            float4* dst = (float4*)e_s;
            for (int i = tid; i < 64 * Dh / 4; i += 256) dst[i] = src[i];
        }
        __syncthreads();
#pragma unroll 2
        for (int jj = 0; jj < 64; jj++) {
            float yv[4], wv[16];
#pragma unroll
            for (int a = 0; a < 4; a++) yv[a] = q_s[(16 * a + ty) * Dh + j0 + jj];
#pragma unroll
            for (int c = 0; c < 16; c++) wv[c] = e_s[jj * Dh + tx + 16 * c];
#pragma unroll
            for (int a = 0; a < 4; a++)
#pragma unroll
                for (int c = 0; c < 16; c++) yacc[a][c] = fmaf(yv[a], wv[c], yacc[a][c]);
        }
        __syncthreads();
    }

    // ---- Store ----
#pragma unroll
    for (int a = 0; a < 4; a++) {
        float* dst = out + (b * Ss + q0 + 16 * a + ty) * Dh;
#pragma unroll
        for (int c = 0; c < 16; c++) dst[tx + 16 * c] = yacc[a][c];
    }
}

extern "C" void kernel_launch(void* const* d_in, const int* in_sizes, int n_in,
                              void* d_out, int out_size) {
    const float* e   = (const float*)d_in[0];
    const float* p   = (const float*)d_in[1];
    const float* W_o = (const float*)d_in[2];
    float* out = (float*)d_out;

    cudaFuncSetAttribute(attn_kernel, cudaFuncAttributeMaxDynamicSharedMemorySize,
                         SMEM_FLOATS * sizeof(float));

    wt_kernel<<<Dh, Dh>>>(W_o);
    dim3 grid(Ss / BQ, Bb);
    attn_kernel<<<grid, 256, SMEM_FLOATS * sizeof(float)>>>(e, p, out);
}

// round 2
// speedup vs baseline: 1.3660x; 1.3660x over previous
#include <cuda_runtime.h>
#include <math.h>

#define Bb 8
#define Ss 2048
#define Dh 256
#define Hh 8
#define BQ 64
#define BK 64
#define QTS 68   // padded row stride for transposed Q and P tiles

// Folded output projection: Wt[j][d] = sum_h W_o[d][h*256 + j]
__device__ float g_Wt[Dh * Dh];

__global__ void wt_kernel(const float* __restrict__ W_o) {
    int d = blockIdx.x;
    int j = threadIdx.x;
    float s = 0.f;
#pragma unroll
    for (int h = 0; h < Hh; h++) s += W_o[d * (Dh * Hh) + h * Dh + j];
    g_Wt[j * Dh + d] = s;
}

// ---- f32x2 helpers ----
typedef unsigned long long u64;

__device__ __forceinline__ u64 pk2(float lo, float hi) {
    u64 r; asm("mov.b64 %0,{%1,%2};" : "=l"(r) : "f"(lo), "f"(hi)); return r;
}
__device__ __forceinline__ void up2(u64 v, float& lo, float& hi) {
    asm("mov.b64 {%0,%1},%2;" : "=f"(lo), "=f"(hi) : "l"(v));
}
__device__ __forceinline__ void fma2(u64& acc, u64 a, u64 b) {
    asm("fma.rn.f32x2 %0,%1,%2,%0;" : "+l"(acc) : "l"(a), "l"(b));
}
__device__ __forceinline__ void lds2(const float* ptr, u64& a, u64& b) {
    unsigned s = (unsigned)__cvta_generic_to_shared(ptr);
    asm volatile("ld.shared.v2.b64 {%0,%1},[%2];" : "=l"(a), "=l"(b) : "r"(s));
}

// Shared memory layout (floats)
#define OFF_QT 0                         // 256 x 68 = 17408
#define OFF_K  (Dh * QTS)                // 64 x 256 = 16384 (reused as y_s)
#define OFF_E  (OFF_K + BK * Dh)         // 64 x 256 = 16384 (reused as w_s)
#define OFF_P  (OFF_E + BK * Dh)         // 64 x 68  = 4352  (P transposed [k][q])
#define SMEM_FLOATS (OFF_P + BK * QTS)   // 54528 floats = 218112 B

extern __shared__ float sm[];

__global__ __launch_bounds__(256, 1) void attn_kernel(
    const float* __restrict__ e,
    const float* __restrict__ p,
    float* __restrict__ out)
{
    const int qb = (Ss / BQ - 1) - blockIdx.x;   // longest-first scheduling
    const int b  = blockIdx.y;
    const int q0 = qb * BQ;
    const int tid = threadIdx.x;
    const int tx = tid & 15;
    const int ty = tid >> 4;

    float* qT_s = sm + OFF_QT;  // [256 d][68] transposed Q
    float* k_s  = sm + OFF_K;   // [64][256] row-major K  (later y_s)
    float* e_s  = sm + OFF_E;   // [64][256] row-major E  (later w_s)
    float* P_s  = sm + OFF_P;   // [64 k][68 q] P transposed

    // ---- Load + transpose Q once: q row r = p[b][1 + q0 + r][:] ----
    {
        const float4* src = (const float4*)(p + (size_t)(b * (Ss + 1) + 1 + q0) * Dh);
        for (int i = tid; i < BQ * Dh / 4; i += 256) {
            int r = i >> 6, d4 = i & 63;
            float4 v = src[r * 64 + d4];
            int d = d4 * 4;
            qT_s[(d + 0) * QTS + r] = v.x;
            qT_s[(d + 1) * QTS + r] = v.y;
            qT_s[(d + 2) * QTS + r] = v.z;
            qT_s[(d + 3) * QTS + r] = v.w;
        }
    }

    u64 yacc[4][8];
    float den[4];
#pragma unroll
    for (int a = 0; a < 4; a++) {
        den[a] = 0.f;
#pragma unroll
        for (int g = 0; g < 8; g++) yacc[a][g] = pk2(0.f, 0.f);
    }

    const float scale = 0.0625f;  // 1/sqrt(256)

    for (int kb = 0; kb <= qb; kb++) {
        const int k0 = kb * BK;
        __syncthreads();

        // Load E and K tiles, row-major, straight float4 copies
        {
            const float4* srcE = (const float4*)(e + (size_t)(b * Ss + k0) * Dh);
            float4* dstE = (float4*)e_s;
            const float4* srcK = (const float4*)(p + (size_t)(b * (Ss + 1) + k0) * Dh);
            float4* dstK = (float4*)k_s;
            for (int i = tid; i < BK * Dh / 4; i += 256) {
                dstE[i] = srcE[i];
                dstK[i] = srcK[i];
            }
        }
        __syncthreads();

        // ---- Scores (transposed): S^T[k=16a+ty][q=4tx+c] = sum_d K[k][d] Q^T[d][q]
        u64 sacc[4][2];
#pragma unroll
        for (int a = 0; a < 4; a++) { sacc[a][0] = pk2(0.f, 0.f); sacc[a][1] = pk2(0.f, 0.f); }

#pragma unroll 2
        for (int d = 0; d < Dh; d += 4) {
            float k4[4][4];
#pragma unroll
            for (int a = 0; a < 4; a++) {
                float4 t = *(const float4*)&k_s[(16 * a + ty) * Dh + d];
                k4[a][0] = t.x; k4[a][1] = t.y; k4[a][2] = t.z; k4[a][3] = t.w;
            }
            u64 qv[4][2];
#pragma unroll
            for (int dd = 0; dd < 4; dd++)
                lds2(&qT_s[(d + dd) * QTS + 4 * tx], qv[dd][0], qv[dd][1]);
#pragma unroll
            for (int dd = 0; dd < 4; dd++)
#pragma unroll
                for (int a = 0; a < 4; a++) {
                    u64 kk = pk2(k4[a][dd], k4[a][dd]);
                    fma2(sacc[a][0], qv[dd][0], kk);
                    fma2(sacc[a][1], qv[dd][1], kk);
                }
        }

        // clip, (mask on diagonal tile), exp -> P^T in smem
#pragma unroll
        for (int a = 0; a < 4; a++) {
            float s0, s1, s2, s3;
            up2(sacc[a][0], s0, s1);
            up2(sacc[a][1], s2, s3);
            float4 px;
            px.x = __expf(fminf(fmaxf(s0 * scale, -10.f), 10.f));
            px.y = __expf(fminf(fmaxf(s1 * scale, -10.f), 10.f));
            px.z = __expf(fminf(fmaxf(s2 * scale, -10.f), 10.f));
            px.w = __expf(fminf(fmaxf(s3 * scale, -10.f), 10.f));
            if (kb == qb) {  // causal mask only matters on the diagonal tile
                int kpos = k0 + 16 * a + ty;
                int qp = q0 + 4 * tx;
                if (kpos > qp + 0) px.x = 0.f;
                if (kpos > qp + 1) px.y = 0.f;
                if (kpos > qp + 2) px.z = 0.f;
                if (kpos > qp + 3) px.w = 0.f;
            }
            *(float4*)&P_s[(16 * a + ty) * QTS + 4 * tx] = px;
        }
        __syncthreads();

        // ---- AV: y[q=16a+ty][dcol] += P^T[kk][q] * E[kk][dcol], den += rowsum
#pragma unroll 2
        for (int kk = 0; kk < BK; kk++) {
            float pv[4]; u64 pp[4];
#pragma unroll
            for (int a = 0; a < 4; a++) {
                pv[a] = P_s[kk * QTS + 16 * a + ty];
                den[a] += pv[a];
                pp[a] = pk2(pv[a], pv[a]);
            }
#pragma unroll
            for (int g = 0; g < 4; g++) {
                u64 ea, eb;
                lds2(&e_s[kk * Dh + 64 * g + 4 * tx], ea, eb);
#pragma unroll
                for (int a = 0; a < 4; a++) {
                    fma2(yacc[a][2 * g],     ea, pp[a]);
                    fma2(yacc[a][2 * g + 1], eb, pp[a]);
                }
            }
        }
    }

    // ---- Normalize and stage y into smem (reuse k_s region) ----
    __syncthreads();
    float* y_s = k_s;
#pragma unroll
    for (int a = 0; a < 4; a++) {
        float inv = 1.f / (den[a] * (float)(q0 + 16 * a + ty + 1));
#pragma unroll
        for (int g = 0; g < 4; g++) {
            float v0, v1, v2, v3;
            up2(yacc[a][2 * g], v0, v1);
            up2(yacc[a][2 * g + 1], v2, v3);
            float4 w4 = make_float4(v0 * inv, v1 * inv, v2 * inv, v3 * inv);
            *(float4*)&y_s[(16 * a + ty) * Dh + 64 * g + 4 * tx] = w4;
            yacc[a][2 * g] = pk2(0.f, 0.f);
            yacc[a][2 * g + 1] = pk2(0.f, 0.f);
        }
    }

    // ---- Epilogue: out = y @ Wt (Wt stored [j][d]) ----
    float* w_s = e_s;
    for (int jb = 0; jb < 4; jb++) {
        __syncthreads();
        {
            const float4* src = (const float4*)(g_Wt + (size_t)(jb * 64) * Dh);
            float4* dst = (float4*)w_s;
            for (int i = tid; i < 64 * Dh / 4; i += 256) dst[i] = src[i];
        }
        __syncthreads();
#pragma unroll 1
        for (int j = 0; j < 64; j += 4) {
            float y4[4][4];
#pragma unroll
            for (int a = 0; a < 4; a++) {
                float4 t = *(const float4*)&y_s[(16 * a + ty) * Dh + jb * 64 + j];
                y4[a][0] = t.x; y4[a][1] = t.y; y4[a][2] = t.z; y4[a][3] = t.w;
            }
#pragma unroll
            for (int jj = 0; jj < 4; jj++) {
                u64 wv[4][2];
#pragma unroll
                for (int g = 0; g < 4; g++)
                    lds2(&w_s[(j + jj) * Dh + 64 * g + 4 * tx], wv[g][0], wv[g][1]);
#pragma unroll
                for (int a = 0; a < 4; a++) {
                    u64 yy = pk2(y4[a][jj], y4[a][jj]);
#pragma unroll
                    for (int g = 0; g < 4; g++) {
                        fma2(yacc[a][2 * g],     wv[g][0], yy);
                        fma2(yacc[a][2 * g + 1], wv[g][1], yy);
                    }
                }
            }
        }
    }

    // ---- Store output ----
#pragma unroll
    for (int a = 0; a < 4; a++) {
        float* dst = out + ((size_t)b * Ss + q0 + 16 * a + ty) * Dh;
#pragma unroll
        for (int g = 0; g < 4; g++) {
            float v0, v1, v2, v3;
            up2(yacc[a][2 * g], v0, v1);
            up2(yacc[a][2 * g + 1], v2, v3);
            *(float4*)&dst[64 * g + 4 * tx] = make_float4(v0, v1, v2, v3);
        }
    }
}

extern "C" void kernel_launch(void* const* d_in, const int* in_sizes, int n_in,
                              void* d_out, int out_size) {
    const float* e   = (const float*)d_in[0];
    const float* p   = (const float*)d_in[1];
    const float* W_o = (const float*)d_in[2];
    float* out = (float*)d_out;

    cudaFuncSetAttribute(attn_kernel, cudaFuncAttributeMaxDynamicSharedMemorySize,
                         SMEM_FLOATS * sizeof(float));

    wt_kernel<<<Dh, Dh>>>(W_o);
    dim3 grid(Ss / BQ, Bb);
    attn_kernel<<<grid, 256, SMEM_FLOATS * sizeof(float)>>>(e, p, out);
}

// round 3
// speedup vs baseline: 1.3662x; 1.0002x over previous
#include <cuda_runtime.h>
#include <math.h>

#define Bb 8
#define Ss 2048
#define Dh 256
#define Hh 8
#define BQ 64
#define BK 64
#define QTS 68   // padded row stride for transposed Q and P tiles

// Folded output projection: Wt[j][d] = sum_h W_o[d][h*256 + j]
__device__ float g_Wt[Dh * Dh];

__global__ void wt_kernel(const float* __restrict__ W_o) {
    int d = blockIdx.x;
    int j = threadIdx.x;
    float s = 0.f;
#pragma unroll
    for (int h = 0; h < Hh; h++) s += W_o[d * (Dh * Hh) + h * Dh + j];
    g_Wt[j * Dh + d] = s;
}

// ---- f32x2 helpers ----
typedef unsigned long long u64;

__device__ __forceinline__ u64 pk2(float lo, float hi) {
    u64 r; asm("mov.b64 %0,{%1,%2};" : "=l"(r) : "f"(lo), "f"(hi)); return r;
}
__device__ __forceinline__ void up2(u64 v, float& lo, float& hi) {
    asm("mov.b64 {%0,%1},%2;" : "=f"(lo), "=f"(hi) : "l"(v));
}
__device__ __forceinline__ void fma2(u64& acc, u64 a, u64 b) {
    asm("fma.rn.f32x2 %0,%1,%2,%0;" : "+l"(acc) : "l"(a), "l"(b));
}
__device__ __forceinline__ void lds2(const float* ptr, u64& a, u64& b) {
    unsigned s = (unsigned)__cvta_generic_to_shared(ptr);
    asm volatile("ld.shared.v2.b64 {%0,%1},[%2];" : "=l"(a), "=l"(b) : "r"(s));
}

// Shared memory layout (floats)
#define OFF_QT 0                         // 256 x 68 = 17408
#define OFF_K  (Dh * QTS)                // 64 x 256 = 16384 (reused as y_s)
#define OFF_E  (OFF_K + BK * Dh)         // 64 x 256 = 16384 (reused as w_s)
#define OFF_P  (OFF_E + BK * Dh)         // 64 x 68  = 4352  (P transposed [k][q])
#define SMEM_FLOATS (OFF_P + BK * QTS)   // 54528 floats = 218112 B

extern __shared__ float sm[];

__global__ __launch_bounds__(256, 1) void attn_kernel(
    const float* __restrict__ e,
    const float* __restrict__ p,
    float* __restrict__ out)
{
    const int qb = (Ss / BQ - 1) - blockIdx.x;   // longest-first scheduling
    const int b  = blockIdx.y;
    const int q0 = qb * BQ;
    const int tid = threadIdx.x;
    const int tx = tid & 15;
    const int ty = tid >> 4;

    float* qT_s = sm + OFF_QT;  // [256 d][68] transposed Q
    float* k_s  = sm + OFF_K;   // [64][256] row-major K  (later y_s)
    float* e_s  = sm + OFF_E;   // [64][256] row-major E  (later w_s)
    float* P_s  = sm + OFF_P;   // [64 k][68 q] P transposed

    // ---- Load + transpose Q once: q row r = p[b][1 + q0 + r][:] ----
    {
        const float4* src = (const float4*)(p + (size_t)(b * (Ss + 1) + 1 + q0) * Dh);
        for (int i = tid; i < BQ * Dh / 4; i += 256) {
            int r = i >> 6, d4 = i & 63;
            float4 v = src[r * 64 + d4];
            int d = d4 * 4;
            qT_s[(d + 0) * QTS + r] = v.x;
            qT_s[(d + 1) * QTS + r] = v.y;
            qT_s[(d + 2) * QTS + r] = v.z;
            qT_s[(d + 3) * QTS + r] = v.w;
        }
    }

    u64 yacc[4][8];
    float den[4];
#pragma unroll
    for (int a = 0; a < 4; a++) {
        den[a] = 0.f;
#pragma unroll
        for (int g = 0; g < 8; g++) yacc[a][g] = pk2(0.f, 0.f);
    }

    const float scale = 0.0625f;  // 1/sqrt(256)

    for (int kb = 0; kb <= qb; kb++) {
        const int k0 = kb * BK;
        __syncthreads();

        // Load E and K tiles, row-major, straight float4 copies
        {
            const float4* srcE = (const float4*)(e + (size_t)(b * Ss + k0) * Dh);
            float4* dstE = (float4*)e_s;
            const float4* srcK = (const float4*)(p + (size_t)(b * (Ss + 1) + k0) * Dh);
            float4* dstK = (float4*)k_s;
            for (int i = tid; i < BK * Dh / 4; i += 256) {
                dstE[i] = srcE[i];
                dstK[i] = srcK[i];
            }
        }
        __syncthreads();

        // ---- Scores (transposed): S^T[k=16a+ty][q=4tx+c] = sum_d K[k][d] Q^T[d][q]
        u64 sacc[4][2];
#pragma unroll
        for (int a = 0; a < 4; a++) { sacc[a][0] = pk2(0.f, 0.f); sacc[a][1] = pk2(0.f, 0.f); }

#pragma unroll 2
        for (int d = 0; d < Dh; d += 4) {
            float k4[4][4];
#pragma unroll
            for (int a = 0; a < 4; a++) {
                float4 t = *(const float4*)&k_s[(16 * a + ty) * Dh + d];
                k4[a][0] = t.x; k4[a][1] = t.y; k4[a][2] = t.z; k4[a][3] = t.w;
            }
            u64 qv[4][2];
#pragma unroll
            for (int dd = 0; dd < 4; dd++)
                lds2(&qT_s[(d + dd) * QTS + 4 * tx], qv[dd][0], qv[dd][1]);
#pragma unroll
            for (int dd = 0; dd < 4; dd++)
#pragma unroll
                for (int a = 0; a < 4; a++) {
                    u64 kk = pk2(k4[a][dd], k4[a][dd]);
                    fma2(sacc[a][0], qv[dd][0], kk);
                    fma2(sacc[a][1], qv[dd][1], kk);
                }
        }

        // clip, (mask on diagonal tile), exp -> P^T in smem
#pragma unroll
        for (int a = 0; a < 4; a++) {
            float s0, s1, s2, s3;
            up2(sacc[a][0], s0, s1);
            up2(sacc[a][1], s2, s3);
            float4 px;
            px.x = __expf(fminf(fmaxf(s0 * scale, -10.f), 10.f));
            px.y = __expf(fminf(fmaxf(s1 * scale, -10.f), 10.f));
            px.z = __expf(fminf(fmaxf(s2 * scale, -10.f), 10.f));
            px.w = __expf(fminf(fmaxf(s3 * scale, -10.f), 10.f));
            if (kb == qb) {  // causal mask only matters on the diagonal tile
                int kpos = k0 + 16 * a + ty;
                int qp = q0 + 4 * tx;
                if (kpos > qp + 0) px.x = 0.f;
                if (kpos > qp + 1) px.y = 0.f;
                if (kpos > qp + 2) px.z = 0.f;
                if (kpos > qp + 3) px.w = 0.f;
            }
            *(float4*)&P_s[(16 * a + ty) * QTS + 4 * tx] = px;
        }
        __syncthreads();

        // ---- AV: y[q=16a+ty][dcol] += P^T[kk][q] * E[kk][dcol], den += rowsum
#pragma unroll 2
        for (int kk = 0; kk < BK; kk++) {
            float pv[4]; u64 pp[4];
#pragma unroll
            for (int a = 0; a < 4; a++) {
                pv[a] = P_s[kk * QTS + 16 * a + ty];
                den[a] += pv[a];
                pp[a] = pk2(pv[a], pv[a]);
            }
#pragma unroll
            for (int g = 0; g < 4; g++) {
                u64 ea, eb;
                lds2(&e_s[kk * Dh + 64 * g + 4 * tx], ea, eb);
#pragma unroll
                for (int a = 0; a < 4; a++) {
                    fma2(yacc[a][2 * g],     ea, pp[a]);
                    fma2(yacc[a][2 * g + 1], eb, pp[a]);
                }
            }
        }
    }

    // ---- Normalize and stage y into smem (reuse k_s region) ----
    __syncthreads();
    float* y_s = k_s;
#pragma unroll
    for (int a = 0; a < 4; a++) {
        float inv = 1.f / (den[a] * (float)(q0 + 16 * a + ty + 1));
#pragma unroll
        for (int g = 0; g < 4; g++) {
            float v0, v1, v2, v3;
            up2(yacc[a][2 * g], v0, v1);
            up2(yacc[a][2 * g + 1], v2, v3);
            float4 w4 = make_float4(v0 * inv, v1 * inv, v2 * inv, v3 * inv);
            *(float4*)&y_s[(16 * a + ty) * Dh + 64 * g + 4 * tx] = w4;
            yacc[a][2 * g] = pk2(0.f, 0.f);
            yacc[a][2 * g + 1] = pk2(0.f, 0.f);
        }
    }

    // ---- Epilogue: out = y @ Wt (Wt stored [j][d]) ----
    float* w_s = e_s;
    for (int jb = 0; jb < 4; jb++) {
        __syncthreads();
        {
            const float4* src = (const float4*)(g_Wt + (size_t)(jb * 64) * Dh);
            float4* dst = (float4*)w_s;
            for (int i = tid; i < 64 * Dh / 4; i += 256) dst[i] = src[i];
        }
        __syncthreads();
#pragma unroll 1
        for (int j = 0; j < 64; j += 4) {
            float y4[4][4];
#pragma unroll
            for (int a = 0; a < 4; a++) {
                float4 t = *(const float4*)&y_s[(16 * a + ty) * Dh + jb * 64 + j];
                y4[a][0] = t.x; y4[a][1] = t.y; y4[a][2] = t.z; y4[a][3] = t.w;
            }
#pragma unroll
            for (int jj = 0; jj < 4; jj++) {
                u64 wv[4][2];
#pragma unroll
                for (int g = 0; g < 4; g++)
                    lds2(&w_s[(j + jj) * Dh + 64 * g + 4 * tx], wv[g][0], wv[g][1]);
#pragma unroll
                for (int a = 0; a < 4; a++) {
                    u64 yy = pk2(y4[a][jj], y4[a][jj]);
#pragma unroll
                    for (int g = 0; g < 4; g++) {
                        fma2(yacc[a][2 * g],     wv[g][0], yy);
                        fma2(yacc[a][2 * g + 1], wv[g][1], yy);
                    }
                }
            }
        }
    }

    // ---- Store output ----
#pragma unroll
    for (int a = 0; a < 4; a++) {
        float* dst = out + ((size_t)b * Ss + q0 + 16 * a + ty) * Dh;
#pragma unroll
        for (int g = 0; g < 4; g++) {
            float v0, v1, v2, v3;
            up2(yacc[a][2 * g], v0, v1);
            up2(yacc[a][2 * g + 1], v2, v3);
            *(float4*)&dst[64 * g + 4 * tx] = make_float4(v0, v1, v2, v3);
        }
    }
}

extern "C" void kernel_launch(void* const* d_in, const int* in_sizes, int n_in,
                              void* d_out, int out_size) {
    const float* e   = (const float*)d_in[0];
    const float* p   = (const float*)d_in[1];
    const float* W_o = (const float*)d_in[2];
    float* out = (float*)d_out;

    cudaFuncSetAttribute(attn_kernel, cudaFuncAttributeMaxDynamicSharedMemorySize,
                         SMEM_FLOATS * sizeof(float));

    wt_kernel<<<Dh, Dh>>>(W_o);
    dim3 grid(Ss / BQ, Bb);
    attn_kernel<<<grid, 256, SMEM_FLOATS * sizeof(float)>>>(e, p, out);
}

// round 5
// speedup vs baseline: 3.3836x; 2.4766x over previous
#include <cuda_runtime.h>
#include <cuda_bf16.h>
#include <stdint.h>

#define Ss 2048
#define Dh 256

__device__ float g_W2[256 * 256];   // folded W: W2[j][dout] = sum_h W_o[dout][h*256+j]

// ---------------- helpers ----------------
__device__ __forceinline__ uint32_t smem_u32(const void* p) {
    uint32_t a; asm("{.reg .u64 t; cvta.to.shared.u64 t,%1; cvt.u32.u64 %0,t;}" : "=r"(a) : "l"(p)); return a;
}
__device__ __forceinline__ uint32_t bfpk(float a, float b) {  // low=a, high=b
    uint32_t r; asm("cvt.rn.bf16x2.f32 %0,%1,%2;" : "=r"(r) : "f"(b), "f"(a)); return r;
}
__device__ __forceinline__ void split2(float a, float b, uint32_t& hi, uint32_t& lo) {
    hi = bfpk(a, b);
    float ha = __uint_as_float(hi << 16), hb = __uint_as_float(hi & 0xFFFF0000u);
    lo = bfpk(a - ha, b - hb);
}
__device__ __forceinline__ void mmaf(float* c, const uint32_t* a, const uint32_t* b) {
    asm volatile("mma.sync.aligned.m16n8k16.row.col.f32.bf16.bf16.f32 "
        "{%0,%1,%2,%3},{%4,%5,%6,%7},{%8,%9},{%0,%1,%2,%3};"
        : "+f"(c[0]), "+f"(c[1]), "+f"(c[2]), "+f"(c[3])
        : "r"(a[0]), "r"(a[1]), "r"(a[2]), "r"(a[3]), "r"(b[0]), "r"(b[1]));
}
__device__ __forceinline__ void ldsm4(uint32_t* r, uint32_t a) {
    asm volatile("ldmatrix.sync.aligned.m8n8.x4.shared.b16 {%0,%1,%2,%3},[%4];"
        : "=r"(r[0]), "=r"(r[1]), "=r"(r[2]), "=r"(r[3]) : "r"(a));
}
__device__ __forceinline__ void ldsm2(uint32_t* r, uint32_t a) {
    asm volatile("ldmatrix.sync.aligned.m8n8.x2.shared.b16 {%0,%1},[%2];"
        : "=r"(r[0]), "=r"(r[1]) : "r"(a));
}
__device__ __forceinline__ void ldsm2t(uint32_t* r, uint32_t a) {
    asm volatile("ldmatrix.sync.aligned.m8n8.x2.trans.shared.b16 {%0,%1},[%2];"
        : "=r"(r[0]), "=r"(r[1]) : "r"(a));
}
__device__ __forceinline__ float expclip(float s) {
    return __expf(fminf(fmaxf(s * 0.0625f, -10.f), 10.f));
}

// f32 [64][256] tile -> bf16 hi/lo tiles with padded row stride 264 (528 B)
__device__ __forceinline__ void load_tile(const float4* __restrict__ src,
                                          unsigned char* dh, unsigned char* dl, int tid) {
#pragma unroll
    for (int t = 0; t < 16; t++) {
        int i = tid + 256 * t;
        int r = i >> 6, c4 = i & 63;
        float4 v = src[i];
        uint32_t h0, l0, h1, l1;
        split2(v.x, v.y, h0, l0);
        split2(v.z, v.w, h1, l1);
        uint32_t off = (uint32_t)r * 528 + (uint32_t)c4 * 8;
        *(uint2*)(dh + off) = make_uint2(h0, h1);
        *(uint2*)(dl + off) = make_uint2(l0, l1);
    }
}

// smem byte offsets
#define SQH 0u
#define SQL 33792u
#define SBH 67584u
#define SBL 101376u
#define SPH 135168u
#define SPL 144384u
#define SD0 153600u
#define SMEM_BYTES 154112u

__global__ void wt_kernel(const float* __restrict__ W_o) {
    int j = blockIdx.x, dout = threadIdx.x;
    float s = 0.f;
#pragma unroll
    for (int h = 0; h < 8; h++) s += W_o[(size_t)dout * 2048 + h * 256 + j];
    g_W2[j * 256 + dout] = s;
}

__global__ __launch_bounds__(256, 1) void attn_kernel(
    const float* __restrict__ ein,
    const float* __restrict__ pin,
    float* __restrict__ out)
{
    extern __shared__ unsigned char smp[];
    const uint32_t sb = smem_u32(smp);
    const int tid = threadIdx.x, w = tid >> 5, l = tid & 31;
    const int qb = 31 - (int)blockIdx.x, b = blockIdx.y;
    const int q0 = qb * 64;
    const int m0 = 16 * (w & 3);      // warp's row tile
    const int half = w >> 2;          // S: n-half (32 cols); AV/epi: col-half (128 cols)

    // ldmatrix address components
    const uint32_t la7 = l & 7, sel = l >> 3;
    const uint32_t aRow = m0 + la7 + (sel & 1) * 8;
    const uint32_t aColB = (sel >> 1) * 8;
    const uint32_t qoff = aRow * 528 + aColB * 2;   // A-frag offset in Q/ynorm region
    const uint32_t poff = aRow * 144 + aColB * 2;   // A-frag offset in P region
    const uint32_t bsoff = (32 * half + la7) * 528 + ((sel & 1) * 8) * 2;  // K B-frag (x2)
    const uint32_t beoff = (uint32_t)(l & 15) * 528;                        // E/W B-frag (x2 trans)

    // Load Q tile once
    load_tile((const float4*)(pin + ((size_t)b * (Ss + 1) + q0 + 1) * Dh),
              smp + SQH, smp + SQL, tid);

    float yacc[16][4];
#pragma unroll
    for (int nt = 0; nt < 16; nt++)
#pragma unroll
        for (int j = 0; j < 4; j++) yacc[nt][j] = 0.f;
    float d0 = 0.f, d1 = 0.f;

    for (int kb = 0; kb <= qb; kb++) {
        if (kb) __syncthreads();  // E readers of previous tile done
        load_tile((const float4*)(pin + ((size_t)b * (Ss + 1) + kb * 64) * Dh),
                  smp + SBH, smp + SBL, tid);  // K tile
        __syncthreads();

        // ---- S = Q K^T (warp: 16 rows x 32 cols) ----
        float sacc[4][4];
#pragma unroll
        for (int nt = 0; nt < 4; nt++)
#pragma unroll
            for (int j = 0; j < 4; j++) sacc[nt][j] = 0.f;

#pragma unroll 4
        for (int k0 = 0; k0 < 256; k0 += 16) {
            uint32_t aqh[4], aql[4];
            ldsm4(aqh, sb + SQH + qoff + k0 * 2);
            ldsm4(aql, sb + SQL + qoff + k0 * 2);
#pragma unroll
            for (int nt = 0; nt < 4; nt++) {
                uint32_t bh[2], bl[2];
                uint32_t bo = bsoff + (uint32_t)nt * (8 * 528) + k0 * 2;
                ldsm2(bh, sb + SBH + bo);
                ldsm2(bl, sb + SBL + bo);
                mmaf(sacc[nt], aqh, bh);
                mmaf(sacc[nt], aqh, bl);
                mmaf(sacc[nt], aql, bh);
            }
        }

        // ---- exp/mask, accumulate den, split P -> smem ----
        {
            const int qr0 = q0 + m0 + (l >> 2), qr1 = qr0 + 8;
            const int cb = kb * 64 + 32 * half + 2 * (l & 3);
            const uint32_t prow0 = (m0 + (l >> 2)) * 144;
#pragma unroll
            for (int nt = 0; nt < 4; nt++) {
                int c0 = cb + 8 * nt, c1 = c0 + 1;
                float p00 = (c0 <= qr0) ? expclip(sacc[nt][0]) : 0.f;
                float p01 = (c1 <= qr0) ? expclip(sacc[nt][1]) : 0.f;
                float p10 = (c0 <= qr1) ? expclip(sacc[nt][2]) : 0.f;
                float p11 = (c1 <= qr1) ? expclip(sacc[nt][3]) : 0.f;
                d0 += p00 + p01;
                d1 += p10 + p11;
                uint32_t coloff = (32 * half + 8 * nt + 2 * (l & 3)) * 2;
                uint32_t h, lo;
                split2(p00, p01, h, lo);
                *(uint32_t*)(smp + SPH + prow0 + coloff) = h;
                *(uint32_t*)(smp + SPL + prow0 + coloff) = lo;
                split2(p10, p11, h, lo);
                *(uint32_t*)(smp + SPH + prow0 + 8 * 144 + coloff) = h;
                *(uint32_t*)(smp + SPL + prow0 + 8 * 144 + coloff) = lo;
            }
        }
        __syncthreads();  // P complete, K reads done
        load_tile((const float4*)(ein + ((size_t)b * Ss + kb * 64) * Dh),
                  smp + SBH, smp + SBL, tid);  // E tile
        __syncthreads();

        // ---- y += P E (warp: 16 rows x 128 cols) ----
#pragma unroll
        for (int k = 0; k < 4; k++) {
            uint32_t aph[4], apl[4];
            ldsm4(aph, sb + SPH + poff + k * 32);
            ldsm4(apl, sb + SPL + poff + k * 32);
#pragma unroll
            for (int nt = 0; nt < 16; nt++) {
                uint32_t bo = beoff + (uint32_t)k * (16 * 528) + (128 * half + 8 * nt) * 2;
                uint32_t bh[2], bl[2];
                ldsm2t(bh, sb + SBH + bo);
                ldsm2t(bl, sb + SBL + bo);
                mmaf(yacc[nt], aph, bh);
                mmaf(yacc[nt], aph, bl);
                mmaf(yacc[nt], apl, bh);
            }
        }
    }

    // ---- den reduce + normalize ----
    d0 += __shfl_xor_sync(~0u, d0, 1); d0 += __shfl_xor_sync(~0u, d0, 2);
    d1 += __shfl_xor_sync(~0u, d1, 1); d1 += __shfl_xor_sync(~0u, d1, 2);
    {
        float* dptr = (float*)(smp + SD0 + half * 256);
        if ((l & 3) == 0) {
            dptr[m0 + (l >> 2)] = d0;
            dptr[m0 + 8 + (l >> 2)] = d1;
        }
    }
    __syncthreads();
    float inv0, inv1;
    {
        float* dn0 = (float*)(smp + SD0);
        float* dn1 = (float*)(smp + SD0 + 256);
        int r0 = m0 + (l >> 2);
        inv0 = 1.f / ((dn0[r0] + dn1[r0]) * (float)(q0 + r0 + 1));
        inv1 = 1.f / ((dn0[r0 + 8] + dn1[r0 + 8]) * (float)(q0 + r0 + 9));
    }

    // stage normalized y into Q region (bf16 split), reset accumulators
    {
        uint32_t rb0 = (m0 + (l >> 2)) * 528;
#pragma unroll
        for (int nt = 0; nt < 16; nt++) {
            uint32_t coloff = (128 * half + 8 * nt + 2 * (l & 3)) * 2;
            uint32_t h, lo;
            split2(yacc[nt][0] * inv0, yacc[nt][1] * inv0, h, lo);
            *(uint32_t*)(smp + SQH + rb0 + coloff) = h;
            *(uint32_t*)(smp + SQL + rb0 + coloff) = lo;
            split2(yacc[nt][2] * inv1, yacc[nt][3] * inv1, h, lo);
            *(uint32_t*)(smp + SQH + rb0 + 8 * 528 + coloff) = h;
            *(uint32_t*)(smp + SQL + rb0 + 8 * 528 + coloff) = lo;
#pragma unroll
            for (int j = 0; j < 4; j++) yacc[nt][j] = 0.f;
        }
    }
    __syncthreads();

    // ---- epilogue: out = ynorm @ W2 ----
    for (int c4 = 0; c4 < 4; c4++) {
        load_tile((const float4*)(g_W2 + (size_t)c4 * 64 * 256),
                  smp + SBH, smp + SBL, tid);
        __syncthreads();
#pragma unroll
        for (int k = 0; k < 4; k++) {
            uint32_t ayh[4], ayl[4];
            uint32_t ao = qoff + (c4 * 64 + k * 16) * 2;
            ldsm4(ayh, sb + SQH + ao);
            ldsm4(ayl, sb + SQL + ao);
#pragma unroll
            for (int nt = 0; nt < 16; nt++) {
                uint32_t bo = beoff + (uint32_t)k * (16 * 528) + (128 * half + 8 * nt) * 2;
                uint32_t bh[2], bl[2];
                ldsm2t(bh, sb + SBH + bo);
                ldsm2t(bl, sb + SBL + bo);
                mmaf(yacc[nt], ayh, bh);
                mmaf(yacc[nt], ayh, bl);
                mmaf(yacc[nt], ayl, bh);
            }
        }
        __syncthreads();
    }

    // ---- store ----
    {
        const int r0 = q0 + m0 + (l >> 2);
#pragma unroll
        for (int nt = 0; nt < 16; nt++) {
            int col = 128 * half + 8 * nt + 2 * (l & 3);
            float* o = out + ((size_t)b * Ss + r0) * Dh + col;
            *(float2*)o = make_float2(yacc[nt][0], yacc[nt][1]);
            *(float2*)(o + 8 * Dh) = make_float2(yacc[nt][2], yacc[nt][3]);
        }
    }
}

extern "C" void kernel_launch(void* const* d_in, const int* in_sizes, int n_in,
                              void* d_out, int out_size) {
    const float* e   = (const float*)d_in[0];
    const float* p   = (const float*)d_in[1];
    const float* W_o = (const float*)d_in[2];
    float* out = (float*)d_out;

    cudaFuncSetAttribute(attn_kernel, cudaFuncAttributeMaxDynamicSharedMemorySize, SMEM_BYTES);

    wt_kernel<<<256, 256>>>(W_o);
    attn_kernel<<<dim3(32, 8), 256, SMEM_BYTES>>>(e, p, out);
}

// round 6
// speedup vs baseline: 3.5436x; 1.0473x over previous
#include <cuda_runtime.h>
#include <cuda_bf16.h>
#include <stdint.h>

#define Ss 2048
#define Dh 256
#define IMGB 67584u   // one tile image: hi[64*528] || lo[64*528]

__device__ float g_W2[256 * 256];
__device__ __align__(16) unsigned char g_qimg[8 * 32 * IMGB];
__device__ __align__(16) unsigned char g_kimg[8 * 32 * IMGB];
__device__ __align__(16) unsigned char g_eimg[8 * 32 * IMGB];
__device__ __align__(16) unsigned char g_wimg[4 * IMGB];

// ---------------- helpers ----------------
__device__ __forceinline__ uint32_t smem_u32(const void* p) {
    uint32_t a; asm("{.reg .u64 t; cvta.to.shared.u64 t,%1; cvt.u32.u64 %0,t;}" : "=r"(a) : "l"(p)); return a;
}
__device__ __forceinline__ uint32_t bfpk(float a, float b) {
    uint32_t r; asm("cvt.rn.bf16x2.f32 %0,%1,%2;" : "=r"(r) : "f"(b), "f"(a)); return r;
}
__device__ __forceinline__ void split2(float a, float b, uint32_t& hi, uint32_t& lo) {
    hi = bfpk(a, b);
    float ha = __uint_as_float(hi << 16), hb = __uint_as_float(hi & 0xFFFF0000u);
    lo = bfpk(a - ha, b - hb);
}
__device__ __forceinline__ void mmaf(float* c, const uint32_t* a, const uint32_t* b) {
    asm volatile("mma.sync.aligned.m16n8k16.row.col.f32.bf16.bf16.f32 "
        "{%0,%1,%2,%3},{%4,%5,%6,%7},{%8,%9},{%0,%1,%2,%3};"
        : "+f"(c[0]), "+f"(c[1]), "+f"(c[2]), "+f"(c[3])
        : "r"(a[0]), "r"(a[1]), "r"(a[2]), "r"(a[3]), "r"(b[0]), "r"(b[1]));
}
__device__ __forceinline__ void ldsm4(uint32_t* r, uint32_t a) {
    asm volatile("ldmatrix.sync.aligned.m8n8.x4.shared.b16 {%0,%1,%2,%3},[%4];"
        : "=r"(r[0]), "=r"(r[1]), "=r"(r[2]), "=r"(r[3]) : "r"(a));
}
__device__ __forceinline__ void ldsm4t(uint32_t* r, uint32_t a) {
    asm volatile("ldmatrix.sync.aligned.m8n8.x4.trans.shared.b16 {%0,%1,%2,%3},[%4];"
        : "=r"(r[0]), "=r"(r[1]), "=r"(r[2]), "=r"(r[3]) : "r"(a));
}
__device__ __forceinline__ float expclip(float s) {
    return __expf(fminf(fmaxf(s * 0.0625f, -10.f), 10.f));
}
__device__ __forceinline__ void cpa16(uint32_t dst, const void* src) {
    asm volatile("cp.async.cg.shared.global [%0],[%1],16;" :: "r"(dst), "l"(src));
}
#define CP_COMMIT() asm volatile("cp.async.commit_group;" ::: "memory")
#define CP_WAIT1()  asm volatile("cp.async.wait_group 1;" ::: "memory")
#define CP_WAIT0()  asm volatile("cp.async.wait_group 0;" ::: "memory")

__device__ __forceinline__ void load_img(uint32_t dst, const unsigned char* src, int tid) {
    for (int i = tid; i < 4224; i += 256)
        cpa16(dst + (uint32_t)i * 16, src + (size_t)i * 16);
}

// f32 [64][256] -> split bf16 image (hi||lo, 528B rows)
__device__ __forceinline__ void img_write(const float4* __restrict__ src,
                                          unsigned char* dst, int tid) {
    unsigned char* dl = dst + 33792;
#pragma unroll
    for (int t = 0; t < 16; t++) {
        int i = tid + 256 * t;
        int r = i >> 6, c4 = i & 63;
        float4 v = src[i];
        uint32_t h0, l0, h1, l1;
        split2(v.x, v.y, h0, l0);
        split2(v.z, v.w, h1, l1);
        uint32_t off = (uint32_t)r * 528 + (uint32_t)c4 * 8;
        *(uint2*)(dst + off) = make_uint2(h0, h1);
        *(uint2*)(dl + off) = make_uint2(l0, l1);
    }
}

// ---------------- prologue kernels ----------------
__global__ void wt_kernel(const float* __restrict__ W_o) {
    int j = blockIdx.x, dout = threadIdx.x;
    float s = 0.f;
#pragma unroll
    for (int h = 0; h < 8; h++) s += W_o[(size_t)dout * 2048 + h * 256 + j];
    g_W2[j * 256 + dout] = s;
}
__global__ void split_p_kernel(const float* __restrict__ p) {
    int t = blockIdx.x, b = blockIdx.y, isq = blockIdx.z;
    const float4* src = (const float4*)(p + ((size_t)(b * (Ss + 1) + t * 64 + isq)) * Dh);
    unsigned char* dst = (isq ? g_qimg : g_kimg) + (size_t)(b * 32 + t) * IMGB;
    img_write(src, dst, threadIdx.x);
}
__global__ void split_e_kernel(const float* __restrict__ e) {
    int t = blockIdx.x, b = blockIdx.y;
    const float4* src = (const float4*)(e + ((size_t)(b * Ss + t * 64)) * Dh);
    img_write(src, g_eimg + (size_t)(b * 32 + t) * IMGB, threadIdx.x);
}
__global__ void split_w_kernel() {
    int c4 = blockIdx.x;
    img_write((const float4*)(g_W2 + (size_t)c4 * 64 * 256),
              g_wimg + (size_t)c4 * IMGB, threadIdx.x);
}

// ---------------- main kernel ----------------
// smem byte offsets
#define SQ   0u
#define SB0  67584u
#define SB1  135168u
#define SPH  202752u
#define SPL  211968u
#define SDEN 221184u
#define SMEM_BYTES 221696u
#define HL 33792u   // hi->lo offset within an image

__global__ __launch_bounds__(256, 1) void attn_kernel(float* __restrict__ out) {
    extern __shared__ unsigned char smp[];
    const uint32_t sb = smem_u32(smp);
    const int tid = threadIdx.x, w = tid >> 5, l = tid & 31;
    const int qb = 31 - (int)blockIdx.x, b = blockIdx.y;
    const int q0 = qb * 64, cnt = qb + 1;
    const int m0 = 16 * (w & 3);
    const int half = w >> 2;

    const uint32_t la7 = l & 7, sel = l >> 3;
    const uint32_t aRow = m0 + la7 + (sel & 1) * 8;
    const uint32_t aColB = (sel >> 1) * 8;
    const uint32_t qoff = aRow * 528 + aColB * 2;
    const uint32_t poff = aRow * 144 + aColB * 2;
    const uint32_t boff4 = (32 * half + la7 + ((l >> 4) & 1) * 8) * 528 + ((l >> 3) & 1) * 16;
    const uint32_t beoff4 = (uint32_t)(l & 15) * 528 + ((l >> 4) & 1) * 16;

    const unsigned char* kim = g_kimg + (size_t)(b * 32) * IMGB;
    const unsigned char* eim = g_eimg + (size_t)(b * 32) * IMGB;

    // pipeline prologue: (Q + K0) group, then E0 group
    load_img(sb + SQ, g_qimg + (size_t)(b * 32 + qb) * IMGB, tid);
    load_img(sb + SB0, kim, tid);
    CP_COMMIT();
    load_img(sb + SB1, eim, tid);
    CP_COMMIT();

    float yacc[16][4];
#pragma unroll
    for (int nt = 0; nt < 16; nt++)
#pragma unroll
        for (int j = 0; j < 4; j++) yacc[nt][j] = 0.f;
    float d0 = 0.f, d1 = 0.f;

    for (int t = 0; t < cnt; t++) {
        CP_WAIT1();          // K_t (and Q) resident
        __syncthreads();

        // ---- S = Q K^T ----
        float sacc[4][4];
#pragma unroll
        for (int nt = 0; nt < 4; nt++)
#pragma unroll
            for (int j = 0; j < 4; j++) sacc[nt][j] = 0.f;

#pragma unroll 4
        for (int k0 = 0; k0 < 256; k0 += 16) {
            uint32_t aqh[4], aql[4];
            ldsm4(aqh, sb + SQ + qoff + k0 * 2);
            ldsm4(aql, sb + SQ + HL + qoff + k0 * 2);
#pragma unroll
            for (int np = 0; np < 2; np++) {
                uint32_t bh[4], bl[4];
                uint32_t bo = boff4 + (uint32_t)np * (16 * 528) + k0 * 2;
                ldsm4(bh, sb + SB0 + bo);
                ldsm4(bl, sb + SB0 + HL + bo);
                mmaf(sacc[2 * np], aqh, bh);
                mmaf(sacc[2 * np], aqh, bl);
                mmaf(sacc[2 * np], aql, bh);
                mmaf(sacc[2 * np + 1], aqh, bh + 2);
                mmaf(sacc[2 * np + 1], aqh, bl + 2);
                mmaf(sacc[2 * np + 1], aql, bh + 2);
            }
        }

        // ---- exp/mask, den, split P ----
        {
            const int qr0 = q0 + m0 + (l >> 2), qr1 = qr0 + 8;
            const int cb = t * 64 + 32 * half + 2 * (l & 3);
            const uint32_t prow0 = (m0 + (l >> 2)) * 144;
#pragma unroll
            for (int nt = 0; nt < 4; nt++) {
                int c0 = cb + 8 * nt, c1 = c0 + 1;
                float p00 = (c0 <= qr0) ? expclip(sacc[nt][0]) : 0.f;
                float p01 = (c1 <= qr0) ? expclip(sacc[nt][1]) : 0.f;
                float p10 = (c0 <= qr1) ? expclip(sacc[nt][2]) : 0.f;
                float p11 = (c1 <= qr1) ? expclip(sacc[nt][3]) : 0.f;
                d0 += p00 + p01;
                d1 += p10 + p11;
                uint32_t coloff = (32 * half + 8 * nt + 2 * (l & 3)) * 2;
                uint32_t h, lo;
                split2(p00, p01, h, lo);
                *(uint32_t*)(smp + SPH + prow0 + coloff) = h;
                *(uint32_t*)(smp + SPL + prow0 + coloff) = lo;
                split2(p10, p11, h, lo);
                *(uint32_t*)(smp + SPH + prow0 + 8 * 144 + coloff) = h;
                *(uint32_t*)(smp + SPL + prow0 + 8 * 144 + coloff) = lo;
            }
        }
        __syncthreads();     // P ready; SB0 readers done

        if (t + 1 < cnt) {   // prefetch K_{t+1} over AV
            load_img(sb + SB0, kim + (size_t)(t + 1) * IMGB, tid);
            CP_COMMIT();
            CP_WAIT1();      // E_t resident
        } else {
            CP_WAIT0();
        }
        __syncthreads();

        // ---- y += P E ----
#pragma unroll
        for (int k = 0; k < 4; k++) {
            uint32_t aph[4], apl[4];
            ldsm4(aph, sb + SPH + poff + k * 32);
            ldsm4(apl, sb + SPL + poff + k * 32);
#pragma unroll
            for (int np = 0; np < 8; np++) {
                uint32_t bo = beoff4 + (uint32_t)k * (16 * 528) + (128 * half + 16 * np) * 2;
                uint32_t bh[4], bl[4];
                ldsm4t(bh, sb + SB1 + bo);
                ldsm4t(bl, sb + SB1 + HL + bo);
                mmaf(yacc[2 * np], aph, bh);
                mmaf(yacc[2 * np], aph, bl);
                mmaf(yacc[2 * np], apl, bh);
                mmaf(yacc[2 * np + 1], aph, bh + 2);
                mmaf(yacc[2 * np + 1], aph, bl + 2);
                mmaf(yacc[2 * np + 1], apl, bh + 2);
            }
        }
        __syncthreads();     // SB1 readers done
        if (t + 1 < cnt) {   // prefetch E_{t+1} over next QK
            load_img(sb + SB1, eim + (size_t)(t + 1) * IMGB, tid);
            CP_COMMIT();
        }
    }

    // ---- den reduce + inv ----
    d0 += __shfl_xor_sync(~0u, d0, 1); d0 += __shfl_xor_sync(~0u, d0, 2);
    d1 += __shfl_xor_sync(~0u, d1, 1); d1 += __shfl_xor_sync(~0u, d1, 2);
    {
        float* dptr = (float*)(smp + SDEN + half * 256);
        if ((l & 3) == 0) {
            dptr[m0 + (l >> 2)] = d0;
            dptr[m0 + 8 + (l >> 2)] = d1;
        }
    }
    __syncthreads();
    float inv0, inv1;
    {
        float* dn0 = (float*)(smp + SDEN);
        float* dn1 = (float*)(smp + SDEN + 256);
        int r0 = m0 + (l >> 2);
        inv0 = 1.f / ((dn0[r0] + dn1[r0]) * (float)(q0 + r0 + 1));
        inv1 = 1.f / ((dn0[r0 + 8] + dn1[r0 + 8]) * (float)(q0 + r0 + 9));
    }

    // stage normalized y into Q region; start W pipeline
    {
        uint32_t rb0 = (m0 + (l >> 2)) * 528;
#pragma unroll
        for (int nt = 0; nt < 16; nt++) {
            uint32_t coloff = (128 * half + 8 * nt + 2 * (l & 3)) * 2;
            uint32_t h, lo;
            split2(yacc[nt][0] * inv0, yacc[nt][1] * inv0, h, lo);
            *(uint32_t*)(smp + SQ + rb0 + coloff) = h;
            *(uint32_t*)(smp + SQ + HL + rb0 + coloff) = lo;
            split2(yacc[nt][2] * inv1, yacc[nt][3] * inv1, h, lo);
            *(uint32_t*)(smp + SQ + rb0 + 8 * 528 + coloff) = h;
            *(uint32_t*)(smp + SQ + HL + rb0 + 8 * 528 + coloff) = lo;
#pragma unroll
            for (int j = 0; j < 4; j++) yacc[nt][j] = 0.f;
        }
    }
    load_img(sb + SB0, g_wimg, tid); CP_COMMIT();
    load_img(sb + SB1, g_wimg + IMGB, tid); CP_COMMIT();

    // ---- epilogue: out = ynorm @ W2 ----
#pragma unroll 1
    for (int c4 = 0; c4 < 4; c4++) {
        if (c4 == 3) CP_WAIT0(); else CP_WAIT1();
        __syncthreads();
        const uint32_t wb = (c4 & 1) ? (sb + SB1) : (sb + SB0);
#pragma unroll
        for (int k = 0; k < 4; k++) {
            uint32_t ayh[4], ayl[4];
            uint32_t ao = qoff + (c4 * 64 + k * 16) * 2;
            ldsm4(ayh, sb + SQ + ao);
            ldsm4(ayl, sb + SQ + HL + ao);
#pragma unroll
            for (int np = 0; np < 8; np++) {
                uint32_t bo = beoff4 + (uint32_t)k * (16 * 528) + (128 * half + 16 * np) * 2;
                uint32_t bh[4], bl[4];
                ldsm4t(bh, wb + bo);
                ldsm4t(bl, wb + HL + bo);
                mmaf(yacc[2 * np], ayh, bh);
                mmaf(yacc[2 * np], ayh, bl);
                mmaf(yacc[2 * np], ayl, bh);
                mmaf(yacc[2 * np + 1], ayh, bh + 2);
                mmaf(yacc[2 * np + 1], ayh, bl + 2);
                mmaf(yacc[2 * np + 1], ayl, bh + 2);
            }
        }
        __syncthreads();
        if (c4 + 2 < 4) {
            load_img((c4 & 1) ? (sb + SB1) : (sb + SB0),
                     g_wimg + (size_t)(c4 + 2) * IMGB, tid);
            CP_COMMIT();
        }
    }

    // ---- store ----
    {
        const int r0 = q0 + m0 + (l >> 2);
#pragma unroll
        for (int nt = 0; nt < 16; nt++) {
            int col = 128 * half + 8 * nt + 2 * (l & 3);
            float* o = out + ((size_t)b * Ss + r0) * Dh + col;
            *(float2*)o = make_float2(yacc[nt][0], yacc[nt][1]);
            *(float2*)(o + 8 * Dh) = make_float2(yacc[nt][2], yacc[nt][3]);
        }
    }
}

extern "C" void kernel_launch(void* const* d_in, const int* in_sizes, int n_in,
                              void* d_out, int out_size) {
    const float* e   = (const float*)d_in[0];
    const float* p   = (const float*)d_in[1];
    const float* W_o = (const float*)d_in[2];
    float* out = (float*)d_out;

    cudaFuncSetAttribute(attn_kernel, cudaFuncAttributeMaxDynamicSharedMemorySize, SMEM_BYTES);

    wt_kernel<<<256, 256>>>(W_o);
    split_p_kernel<<<dim3(32, 8, 2), 256>>>(p);
    split_e_kernel<<<dim3(32, 8), 256>>>(e);
    split_w_kernel<<<4, 256>>>();
    attn_kernel<<<dim3(32, 8), 256, SMEM_BYTES>>>(out);
}

// round 8
// speedup vs baseline: 3.5953x; 1.0146x over previous
#include <cuda_runtime.h>
#include <cuda_bf16.h>
#include <stdint.h>

#define Ss 2048
#define Dh 256
#define IMG32 33792u   // 32-row split image: hi[32*528] || lo[32*528]
#define HL32  16896u

__device__ float g_W2[256 * 256];
__device__ __align__(16) unsigned char g_qimg[8 * 64 * IMG32];
__device__ __align__(16) unsigned char g_kimg[8 * 64 * IMG32];
__device__ __align__(16) unsigned char g_eimg[8 * 64 * IMG32];
__device__ __align__(16) unsigned char g_wimg[8 * IMG32];

// ---------------- helpers ----------------
__device__ __forceinline__ uint32_t smem_u32(const void* p) {
    uint32_t a; asm("{.reg .u64 t; cvta.to.shared.u64 t,%1; cvt.u32.u64 %0,t;}" : "=r"(a) : "l"(p)); return a;
}
__device__ __forceinline__ uint32_t bfpk(float a, float b) {
    uint32_t r; asm("cvt.rn.bf16x2.f32 %0,%1,%2;" : "=r"(r) : "f"(b), "f"(a)); return r;
}
__device__ __forceinline__ void split2(float a, float b, uint32_t& hi, uint32_t& lo) {
    hi = bfpk(a, b);
    float ha = __uint_as_float(hi << 16), hb = __uint_as_float(hi & 0xFFFF0000u);
    lo = bfpk(a - ha, b - hb);
}
__device__ __forceinline__ void mmaf(float* c, const uint32_t* a, const uint32_t* b) {
    asm volatile("mma.sync.aligned.m16n8k16.row.col.f32.bf16.bf16.f32 "
        "{%0,%1,%2,%3},{%4,%5,%6,%7},{%8,%9},{%0,%1,%2,%3};"
        : "+f"(c[0]), "+f"(c[1]), "+f"(c[2]), "+f"(c[3])
        : "r"(a[0]), "r"(a[1]), "r"(a[2]), "r"(a[3]), "r"(b[0]), "r"(b[1]));
}
__device__ __forceinline__ void ldsm4(uint32_t* r, uint32_t a) {
    asm volatile("ldmatrix.sync.aligned.m8n8.x4.shared.b16 {%0,%1,%2,%3},[%4];"
        : "=r"(r[0]), "=r"(r[1]), "=r"(r[2]), "=r"(r[3]) : "r"(a));
}
__device__ __forceinline__ void ldsm4t(uint32_t* r, uint32_t a) {
    asm volatile("ldmatrix.sync.aligned.m8n8.x4.trans.shared.b16 {%0,%1,%2,%3},[%4];"
        : "=r"(r[0]), "=r"(r[1]), "=r"(r[2]), "=r"(r[3]) : "r"(a));
}
__device__ __forceinline__ float expclip(float s) {
    return __expf(fminf(fmaxf(s * 0.0625f, -10.f), 10.f));
}
__device__ __forceinline__ void cpa16(uint32_t dst, const void* src) {
    asm volatile("cp.async.cg.shared.global [%0],[%1],16;" :: "r"(dst), "l"(src));
}
#define CP_COMMIT() asm volatile("cp.async.commit_group;" ::: "memory")
#define CP_WAIT1()  asm volatile("cp.async.wait_group 1;" ::: "memory")
#define CP_WAIT0()  asm volatile("cp.async.wait_group 0;" ::: "memory")

__device__ __forceinline__ void load_img32(uint32_t dst, const unsigned char* src, int tid) {
    for (int i = tid; i < 2112; i += 128)
        cpa16(dst + (uint32_t)i * 16, src + (size_t)i * 16);
}

// ---------------- prologue kernels ----------------
__global__ void wt_kernel(const float* __restrict__ W_o) {
    int j = blockIdx.x, dout = threadIdx.x;
    float s = 0.f;
#pragma unroll
    for (int h = 0; h < 8; h++) s += W_o[(size_t)dout * 2048 + h * 256 + j];
    g_W2[j * 256 + dout] = s;
}
// f32 [32][256] rows -> split image
__device__ __forceinline__ void img32_write(const float4* __restrict__ src,
                                            unsigned char* dst, int tid) {
    unsigned char* dl = dst + HL32;
#pragma unroll
    for (int k = 0; k < 8; k++) {
        int i = tid + 256 * k;
        int r = i >> 6, c4 = i & 63;
        float4 v = src[i];
        uint32_t h0, l0, h1, l1;
        split2(v.x, v.y, h0, l0);
        split2(v.z, v.w, h1, l1);
        uint32_t off = (uint32_t)r * 528 + (uint32_t)c4 * 8;
        *(uint2*)(dst + off) = make_uint2(h0, h1);
        *(uint2*)(dl + off) = make_uint2(l0, l1);
    }
}
__global__ void split_qke_kernel(const float* __restrict__ p, const float* __restrict__ e) {
    int t = blockIdx.x, b = blockIdx.y, kind = blockIdx.z;
    if (kind == 0)
        img32_write((const float4*)(p + ((size_t)(b * (Ss + 1) + t * 32 + 1)) * Dh),
                    g_qimg + (size_t)(b * 64 + t) * IMG32, threadIdx.x);
    else if (kind == 1)
        img32_write((const float4*)(p + ((size_t)(b * (Ss + 1) + t * 32)) * Dh),
                    g_kimg + (size_t)(b * 64 + t) * IMG32, threadIdx.x);
    else
        img32_write((const float4*)(e + ((size_t)(b * Ss + t * 32)) * Dh),
                    g_eimg + (size_t)(b * 64 + t) * IMG32, threadIdx.x);
}
__global__ void split_w_kernel() {
    int c = blockIdx.x;
    img32_write((const float4*)(g_W2 + (size_t)c * 32 * 256),
                g_wimg + (size_t)c * IMG32, threadIdx.x);
}

// ---------------- main kernel ----------------
#define SQ   0u
#define SB0  33792u
#define SB1  67584u
#define SPH  101376u
#define SPL  103936u
#define SDEN 106496u
#define SMEM_BYTES 106752u
#define PST  80u     // P row stride (bytes)

__global__ __launch_bounds__(128, 2) void attn_kernel(float* __restrict__ out) {
    extern __shared__ unsigned char smp[];
    const uint32_t sb = smem_u32(smp);
    const int tid = threadIdx.x, w = tid >> 5, l = tid & 31;
    const int qt = 63 - (int)blockIdx.x, b = blockIdx.y;
    const int q0 = qt * 32, cnt = qt + 1;
    const int m0 = 16 * (w & 1);     // row half
    const int half = w >> 1;         // col half

    const uint32_t la7 = l & 7, sel = l >> 3;
    const uint32_t aRow = m0 + la7 + (sel & 1) * 8;
    const uint32_t aColB = (sel >> 1) * 8;
    const uint32_t qoff = aRow * 528 + aColB * 2;
    const uint32_t poff = aRow * PST + aColB * 2;
    const uint32_t boff4 = (16 * half + la7 + ((l >> 4) & 1) * 8) * 528 + ((l >> 3) & 1) * 16;
    const uint32_t beoff4 = (uint32_t)(l & 15) * 528 + ((l >> 4) & 1) * 16;

    const unsigned char* kim = g_kimg + (size_t)(b * 64) * IMG32;
    const unsigned char* eim = g_eimg + (size_t)(b * 64) * IMG32;

    // prologue: (Q + K0), then E0
    load_img32(sb + SQ, g_qimg + (size_t)(b * 64 + qt) * IMG32, tid);
    load_img32(sb + SB0, kim, tid);
    CP_COMMIT();
    load_img32(sb + SB1, eim, tid);
    CP_COMMIT();

    float yacc[16][4];
#pragma unroll
    for (int nt = 0; nt < 16; nt++)
#pragma unroll
        for (int j = 0; j < 4; j++) yacc[nt][j] = 0.f;
    float d0 = 0.f, d1 = 0.f;

    for (int t = 0; t < cnt; t++) {
        CP_WAIT1();               // Q + K_t resident
        __syncthreads();

        // ---- S = Q K^T (warp: 16 rows x 16 cols) ----
        float sacc[2][4];
#pragma unroll
        for (int nt = 0; nt < 2; nt++)
#pragma unroll
            for (int j = 0; j < 4; j++) sacc[nt][j] = 0.f;

#pragma unroll 4
        for (int k0 = 0; k0 < 256; k0 += 16) {
            uint32_t aqh[4], aql[4];
            ldsm4(aqh, sb + SQ + qoff + k0 * 2);
            ldsm4(aql, sb + SQ + HL32 + qoff + k0 * 2);
            uint32_t bh[4], bl[4];
            ldsm4(bh, sb + SB0 + boff4 + k0 * 2);
            ldsm4(bl, sb + SB0 + HL32 + boff4 + k0 * 2);
            mmaf(sacc[0], aqh, bh);
            mmaf(sacc[0], aqh, bl);
            mmaf(sacc[0], aql, bh);
            mmaf(sacc[1], aqh, bh + 2);
            mmaf(sacc[1], aqh, bl + 2);
            mmaf(sacc[1], aql, bh + 2);
        }
        __syncthreads();          // K reads done
        if (t + 1 < cnt) {        // prefetch K_{t+1} over exp+AV
            load_img32(sb + SB0, kim + (size_t)(t + 1) * IMG32, tid);
            CP_COMMIT();
        }

        // ---- exp/mask, den, split P ----
        {
            const int qr0 = q0 + m0 + (l >> 2), qr1 = qr0 + 8;
            const int cb = t * 32 + 16 * half + 2 * (l & 3);
            const uint32_t prow0 = (m0 + (l >> 2)) * PST;
#pragma unroll
            for (int nt = 0; nt < 2; nt++) {
                int c0 = cb + 8 * nt, c1 = c0 + 1;
                float p00 = (c0 <= qr0) ? expclip(sacc[nt][0]) : 0.f;
                float p01 = (c1 <= qr0) ? expclip(sacc[nt][1]) : 0.f;
                float p10 = (c0 <= qr1) ? expclip(sacc[nt][2]) : 0.f;
                float p11 = (c1 <= qr1) ? expclip(sacc[nt][3]) : 0.f;
                d0 += p00 + p01;
                d1 += p10 + p11;
                uint32_t coloff = (16 * half + 8 * nt + 2 * (l & 3)) * 2;
                uint32_t h, lo;
                split2(p00, p01, h, lo);
                *(uint32_t*)(smp + SPH + prow0 + coloff) = h;
                *(uint32_t*)(smp + SPL + prow0 + coloff) = lo;
                split2(p10, p11, h, lo);
                *(uint32_t*)(smp + SPH + prow0 + 8 * PST + coloff) = h;
                *(uint32_t*)(smp + SPL + prow0 + 8 * PST + coloff) = lo;
            }
        }
        CP_WAIT1();               // E_t resident (K_{t+1} may still be in flight)
        __syncthreads();          // P visible

        // ---- y += P E (warp: 16 rows x 128 cols) ----
#pragma unroll
        for (int k = 0; k < 2; k++) {
            uint32_t aph[4], apl[4];
            ldsm4(aph, sb + SPH + poff + k * 32);
            ldsm4(apl, sb + SPL + poff + k * 32);
#pragma unroll
            for (int np = 0; np < 8; np++) {
                uint32_t bo = beoff4 + (uint32_t)k * (16 * 528) + (128 * half + 16 * np) * 2;
                uint32_t bh[4], bl[4];
                ldsm4t(bh, sb + SB1 + bo);
                ldsm4t(bl, sb + SB1 + HL32 + bo);
                mmaf(yacc[2 * np], aph, bh);
                mmaf(yacc[2 * np], aph, bl);
                mmaf(yacc[2 * np], apl, bh);
                mmaf(yacc[2 * np + 1], aph, bh + 2);
                mmaf(yacc[2 * np + 1], aph, bl + 2);
                mmaf(yacc[2 * np + 1], apl, bh + 2);
            }
        }
        __syncthreads();          // E reads done
        if (t + 1 < cnt) {        // prefetch E_{t+1} over next QK
            load_img32(sb + SB1, eim + (size_t)(t + 1) * IMG32, tid);
            CP_COMMIT();
        }
    }

    // ---- den reduce + inv ----
    d0 += __shfl_xor_sync(~0u, d0, 1); d0 += __shfl_xor_sync(~0u, d0, 2);
    d1 += __shfl_xor_sync(~0u, d1, 1); d1 += __shfl_xor_sync(~0u, d1, 2);
    {
        float* dptr = (float*)(smp + SDEN + half * 128);
        if ((l & 3) == 0) {
            dptr[m0 + (l >> 2)] = d0;
            dptr[m0 + 8 + (l >> 2)] = d1;
        }
    }
    __syncthreads();
    float inv0, inv1;
    {
        float* dn0 = (float*)(smp + SDEN);
        float* dn1 = (float*)(smp + SDEN + 128);
        int r0 = m0 + (l >> 2);
        inv0 = 1.f / ((dn0[r0] + dn1[r0]) * (float)(q0 + r0 + 1));
        inv1 = 1.f / ((dn0[r0 + 8] + dn1[r0 + 8]) * (float)(q0 + r0 + 9));
    }

    // stage normalized y (split) into SQ; start W pipeline
    {
        uint32_t rb0 = (m0 + (l >> 2)) * 528;
#pragma unroll
        for (int nt = 0; nt < 16; nt++) {
            uint32_t coloff = (128 * half + 8 * nt + 2 * (l & 3)) * 2;
            uint32_t h, lo;
            split2(yacc[nt][0] * inv0, yacc[nt][1] * inv0, h, lo);
            *(uint32_t*)(smp + SQ + rb0 + coloff) = h;
            *(uint32_t*)(smp + SQ + HL32 + rb0 + coloff) = lo;
            split2(yacc[nt][2] * inv1, yacc[nt][3] * inv1, h, lo);
            *(uint32_t*)(smp + SQ + rb0 + 8 * 528 + coloff) = h;
            *(uint32_t*)(smp + SQ + HL32 + rb0 + 8 * 528 + coloff) = lo;
#pragma unroll
            for (int j = 0; j < 4; j++) yacc[nt][j] = 0.f;
        }
    }
    load_img32(sb + SB0, g_wimg, tid); CP_COMMIT();
    load_img32(sb + SB1, g_wimg + IMG32, tid); CP_COMMIT();

    // ---- epilogue: out = ynorm @ W2 (8 chunks of 32 j) ----
#pragma unroll 1
    for (int c = 0; c < 8; c++) {
        if (c == 7) CP_WAIT0(); else CP_WAIT1();
        __syncthreads();
        const uint32_t wb = (c & 1) ? (sb + SB1) : (sb + SB0);
#pragma unroll
        for (int k = 0; k < 2; k++) {
            uint32_t ayh[4], ayl[4];
            uint32_t ao = qoff + (c * 32 + k * 16) * 2;
            ldsm4(ayh, sb + SQ + ao);
            ldsm4(ayl, sb + SQ + HL32 + ao);
#pragma unroll
            for (int np = 0; np < 8; np++) {
                uint32_t bo = beoff4 + (uint32_t)k * (16 * 528) + (128 * half + 16 * np) * 2;
                uint32_t bh[4], bl[4];
                ldsm4t(bh, wb + bo);
                ldsm4t(bl, wb + HL32 + bo);
                mmaf(yacc[2 * np], ayh, bh);
                mmaf(yacc[2 * np], ayh, bl);
                mmaf(yacc[2 * np], ayl, bh);
                mmaf(yacc[2 * np + 1], ayh, bh + 2);
                mmaf(yacc[2 * np + 1], ayh, bl + 2);
                mmaf(yacc[2 * np + 1], ayl, bh + 2);
            }
        }
        __syncthreads();
        if (c + 2 < 8) {
            load_img32((c & 1) ? (sb + SB1) : (sb + SB0),
                       g_wimg + (size_t)(c + 2) * IMG32, tid);
            CP_COMMIT();
        }
    }

    // ---- store ----
    {
        const int r0 = q0 + m0 + (l >> 2);
#pragma unroll
        for (int nt = 0; nt < 16; nt++) {
            int col = 128 * half + 8 * nt + 2 * (l & 3);
            float* o = out + ((size_t)b * Ss + r0) * Dh + col;
            *(float2*)o = make_float2(yacc[nt][0], yacc[nt][1]);
            *(float2*)(o + 8 * Dh) = make_float2(yacc[nt][2], yacc[nt][3]);
        }
    }
}

extern "C" void kernel_launch(void* const* d_in, const int* in_sizes, int n_in,
                              void* d_out, int out_size) {
    const float* e   = (const float*)d_in[0];
    const float* p   = (const float*)d_in[1];
    const float* W_o = (const float*)d_in[2];
    float* out = (float*)d_out;

    cudaFuncSetAttribute(attn_kernel, cudaFuncAttributeMaxDynamicSharedMemorySize, SMEM_BYTES);

    wt_kernel<<<256, 256>>>(W_o);
    split_qke_kernel<<<dim3(64, 8, 3), 256>>>(p, e);
    split_w_kernel<<<8, 256>>>();
    attn_kernel<<<dim3(64, 8), 128, SMEM_BYTES>>>(out);
}